// round 12
// baseline (speedup 1.0000x reference)
#include <cuda_runtime.h>
#include <cstdint>
#include <math.h>

// ---------------------------------------------------------------------------
// Shapes
//   x0: [2, 256, 32^3]   -> 512 channel-slices of 32768 elems
//   x1: [2, 128, 64^3]   -> 256 channel-slices of 262144 elems
//   x2: [2,  64, 128^3]  -> 128 channel-slices of 2097152 elems
// Partial-sum layout (deterministic):
//   x2: 32/slice -> 4096 @ g_part[0]; x1: 4/slice -> 1024 @ g_part[4096];
//   x0: 1/slice  ->  512 @ g_part[5120]
// gap_reduce fires PDL completion at entry; epilogue launched with PSS.
// ---------------------------------------------------------------------------

__device__ __align__(16) float g_part[5632];

__global__ __launch_bounds__(256) void gap_reduce(
    const float* __restrict__ x0,
    const float* __restrict__ x1,
    const float* __restrict__ x2)
{
#if __CUDA_ARCH__ >= 900
    cudaTriggerProgrammaticLaunchCompletion();
#endif
    int bid = blockIdx.x;

    const float4* src;
    int nvec;
    if (bid < 4096) {
        src  = reinterpret_cast<const float4*>(x2) + (size_t)bid * 16384;
        nvec = 16384;
    } else if (bid < 5120) {
        src  = reinterpret_cast<const float4*>(x1) + (size_t)(bid - 4096) * 16384;
        nvec = 16384;
    } else {
        src  = reinterpret_cast<const float4*>(x0) + (size_t)(bid - 5120) * 8192;
        nvec = 8192;
    }

    float s = 0.f;
    #pragma unroll 4
    for (int i = threadIdx.x; i < nvec; i += 256) {
        float4 a = __ldcs(src + i);          // streaming: evict-first in L2
        s += (a.x + a.y) + (a.z + a.w);
    }

    __shared__ float sbuf[8];
    #pragma unroll
    for (int o = 16; o; o >>= 1) s += __shfl_down_sync(0xffffffffu, s, o);
    if ((threadIdx.x & 31) == 0) sbuf[threadIdx.x >> 5] = s;
    __syncthreads();
    if (threadIdx.x < 8) {
        s = sbuf[threadIdx.x];
        #pragma unroll
        for (int o = 4; o; o >>= 1) s += __shfl_down_sync(0x000000ffu, s, o);
        if (threadIdx.x == 0) g_part[bid] = s;
    }
}

// ---------------------------------------------------------------------------
// Epilogue: 1 block, 896 threads (warps 0-13 batch0, 14-27 batch1).
// LN chain in 3 reduction rounds (LN1/2/3 fused as disjoint warp-aligned
// segments; values carried in registers). Weight copies via cp.async.
// Smem row strides: 113 f4 (448-f rows), 17 f4 (64-f rows) -> conflict-free.
// ---------------------------------------------------------------------------

extern __shared__ float4 dynw[];     // 7616 float4 = 121856 B

__device__ __forceinline__ void cp16(uint32_t s, const void* g)
{
    asm volatile("cp.async.cg.shared.global [%0], [%1], 16;" :: "r"(s), "l"(g));
}

__global__ __launch_bounds__(896) void epilogue(
    const float* __restrict__ ln1w, const float* __restrict__ ln1b,
    const float* __restrict__ ln2w, const float* __restrict__ ln2b,
    const float* __restrict__ ln3w, const float* __restrict__ ln3b,
    const float* __restrict__ ln4w, const float* __restrict__ ln4b,
    const float* __restrict__ ln5w, const float* __restrict__ ln5b,
    const float* __restrict__ mlp_w1, const float* __restrict__ mlp_b1,
    const float* __restrict__ mlp_w2, const float* __restrict__ mlp_b2,
    const float* __restrict__ conv_w, const float* __restrict__ conv_b,
    float* __restrict__ out)
{
    __shared__ __align__(16) float sv[2][448];   // final LN out / h2
    __shared__ __align__(16) float h1s[2][64];
    __shared__ __align__(16) float red[2][448];
    __shared__ __align__(16) float s_g[4096];    // staged x2 partials only
    __shared__ float sbuf[56];                   // 28 warps x 2
    __shared__ float s_w[1280];   // ln1@0 ln2@64 ln3@192 ln4@448 ln5@832
    __shared__ float s_b[1280];
    __shared__ float s_b1[64];
    __shared__ float s_b2[448];
    __shared__ float s_bc[64];

    int tid  = threadIdx.x;
    int wid  = tid >> 5;
    int lane = tid & 31;
    uint32_t dynb = (uint32_t)__cvta_generic_to_shared(dynw);

    // ================= PRE-SYNC (overlaps streaming tail via PDL) =========
    {   // L2 prefetch of w2 / wc (896 lines each)
        const char* w2c = (const char*)mlp_w2;
        const char* wcc = (const char*)conv_w;
        size_t off = (size_t)tid * 128;
        asm volatile("prefetch.global.L2 [%0];" :: "l"(w2c + off));
        asm volatile("prefetch.global.L2 [%0];" :: "l"(wcc + off));
    }
    {   // w1 -> dynw via cp.async (113-f4 row stride)
        const float4* g4 = reinterpret_cast<const float4*>(mlp_w1);
        #pragma unroll
        for (int v = tid; v < 7168; v += 896) {
            int row = v / 112;
            int col = v - row * 112;
            cp16(dynb + (uint32_t)(row * 113 + col) * 16u, g4 + v);
        }
        asm volatile("cp.async.commit_group;");
    }
    if (tid < 64)   { s_w[tid]       = ln1w[tid]; s_b[tid]       = ln1b[tid]; }
    if (tid < 128)  { s_w[64 + tid]  = ln2w[tid]; s_b[64 + tid]  = ln2b[tid]; }
    if (tid < 256)  { s_w[192 + tid] = ln3w[tid]; s_b[192 + tid] = ln3b[tid]; }
    if (tid < 384)  { s_w[448 + tid] = ln4w[tid]; s_b[448 + tid] = ln4b[tid]; }
    if (tid < 448)  { s_w[832 + tid] = ln5w[tid]; s_b[832 + tid] = ln5b[tid]; }
    if (tid < 64)   s_b1[tid] = mlp_b1[tid];
    if (tid < 448)  s_b2[tid] = mlp_b2[tid];
    if (tid >= 448 && tid < 512) s_bc[tid - 448] = conv_b[tid - 448];

    // ================= WAIT for gap_reduce ================================
#if __CUDA_ARCH__ >= 900
    cudaGridDependencySynchronize();
#endif
    __syncthreads();

    // --- Stage x2 partials (16 KB) into smem, coalesced ---
    {
        const float4* gp4 = reinterpret_cast<const float4*>(g_part);
        float4* sg4 = reinterpret_cast<float4*>(s_g);
        for (int v = tid; v < 1024; v += 896) sg4[v] = gp4[v];
    }
    __syncthreads();

    int b  = tid / 448;
    int t  = tid - b * 448;
    int wb = b * 14;                  // first warp of this batch group

    // --- Assemble raw GAP mean for channel t (register-resident) ---
    float x;
    if (t < 64) {                     // x2: rotated smem read, conflict-free
        int base = (b * 64 + t) * 32;
        float s = 0.f;
        #pragma unroll
        for (int k = 0; k < 32; k++) s += s_g[base + ((k + t) & 31)];
        x = s * (1.f / 2097152.f);
    } else if (t < 192) {             // x1: one float4 LDG
        const float4* gx1 = reinterpret_cast<const float4*>(g_part + 4096);
        float4 v4 = gx1[b * 128 + (t - 64)];
        x = ((v4.x + v4.y) + (v4.z + v4.w)) * (1.f / 262144.f);
    } else {                          // x0: scalar coalesced LDG
        x = g_part[5120 + b * 256 + (t - 192)] * (1.f / 32768.f);
    }

    // ===================== LN chain: 3 reduction rounds ====================
    // Round A: LN1(64)/LN2(128)/LN3(256) fused — disjoint warp segments.
    {
        float a = x, q = x * x;
        #pragma unroll
        for (int o = 16; o; o >>= 1) {
            a += __shfl_down_sync(0xffffffffu, a, o);
            q += __shfl_down_sync(0xffffffffu, q, o);
        }
        if (lane == 0) { sbuf[wid * 2] = a; sbuf[wid * 2 + 1] = q; }
        __syncthreads();
        int n, w0, wn;
        if (t < 64)       { n = 64;  w0 = wb;     wn = 2; }
        else if (t < 192) { n = 128; w0 = wb + 2; wn = 4; }
        else              { n = 256; w0 = wb + 6; wn = 8; }
        a = 0.f; q = 0.f;
        for (int i = 0; i < wn; i++) { a += sbuf[(w0 + i) * 2]; q += sbuf[(w0 + i) * 2 + 1]; }
        float inv_n = 1.f / (float)n;
        float mu  = a * inv_n;
        float var = fmaxf(q * inv_n - mu * mu, 0.f);
        float r   = rsqrtf(var + 1e-5f);
        x = (x - mu) * r * s_w[t] + s_b[t];      // packed layout aligns with t
    }
    // Round B: LN4 over channels [64,448) (n=384, warps wb+2..wb+13).
    {
        float a = (t >= 64) ? x : 0.f;
        float q = a * x;
        #pragma unroll
        for (int o = 16; o; o >>= 1) {
            a += __shfl_down_sync(0xffffffffu, a, o);
            q += __shfl_down_sync(0xffffffffu, q, o);
        }
        __syncthreads();                          // round-A sbuf reads done
        if (lane == 0) { sbuf[wid * 2] = a; sbuf[wid * 2 + 1] = q; }
        __syncthreads();
        if (t >= 64) {
            float sa = 0.f, sq = 0.f;
            #pragma unroll
            for (int i = 2; i < 14; i++) { sa += sbuf[(wb + i) * 2]; sq += sbuf[(wb + i) * 2 + 1]; }
            float mu  = sa * (1.f / 384.f);
            float var = fmaxf(sq * (1.f / 384.f) - mu * mu, 0.f);
            float r   = rsqrtf(var + 1e-5f);
            x = (x - mu) * r * s_w[448 + (t - 64)] + s_b[448 + (t - 64)];
        }
    }
    // Round C: LN5 over all 448 channels.
    {
        float a = x, q = x * x;
        #pragma unroll
        for (int o = 16; o; o >>= 1) {
            a += __shfl_down_sync(0xffffffffu, a, o);
            q += __shfl_down_sync(0xffffffffu, q, o);
        }
        __syncthreads();
        if (lane == 0) { sbuf[wid * 2] = a; sbuf[wid * 2 + 1] = q; }
        __syncthreads();
        float sa = 0.f, sq = 0.f;
        #pragma unroll
        for (int i = 0; i < 14; i++) { sa += sbuf[(wb + i) * 2]; sq += sbuf[(wb + i) * 2 + 1]; }
        float mu  = sa * (1.f / 448.f);
        float var = fmaxf(sq * (1.f / 448.f) - mu * mu, 0.f);
        float r   = rsqrtf(var + 1e-5f);
        x = (x - mu) * r * s_w[832 + t] + s_b[832 + t];
    }
    sv[b][t] = x;
    asm volatile("cp.async.wait_group 0;");       // w1 resident
    __syncthreads();

    float* svb = sv[b];
    int c = t >> 6;                   // chunk 0..6
    int o = t & 63;                   // output 0..63

    // ======================= Stage 1: W1 dot from smem =====================
    {
        const float4* wr = dynw + o * 113 + c * 16;
        const float4* xr = reinterpret_cast<const float4*>(svb + c * 64);
        float p = 0.f;
        #pragma unroll
        for (int k = 0; k < 16; k++) {
            float4 wv = wr[k], xv = xr[k];
            p = fmaf(wv.x, xv.x, p); p = fmaf(wv.y, xv.y, p);
            p = fmaf(wv.z, xv.z, p); p = fmaf(wv.w, xv.w, p);
        }
        red[b][t] = p;
    }
    __syncthreads();                              // all w1 smem reads done
    // Issue w2 copy (17-f4 stride) while 128 threads finish h1
    {
        const float4* g4 = reinterpret_cast<const float4*>(mlp_w2);
        #pragma unroll
        for (int v = tid; v < 7168; v += 896) {
            int row = v >> 4;
            int col = v & 15;
            cp16(dynb + (uint32_t)(row * 17 + col) * 16u, g4 + v);
        }
        asm volatile("cp.async.commit_group;");
    }
    if (tid < 128) {
        int bb = tid >> 6, oo = tid & 63;
        float acc = s_b1[oo];
        #pragma unroll
        for (int cc = 0; cc < 7; cc++) acc += red[bb][cc * 64 + oo];
        h1s[bb][oo] = fmaxf(acc, 0.f);
    }
    asm volatile("cp.async.wait_group 0;");
    __syncthreads();

    // ======================= Stage 2: W2 dot from smem =====================
    float h2;
    {
        const float4* wr = dynw + t * 17;
        const float4* hr = reinterpret_cast<const float4*>(h1s[b]);
        float acc = s_b2[t];
        #pragma unroll
        for (int k = 0; k < 16; k++) {
            float4 wv = wr[k], hv = hr[k];
            acc = fmaf(wv.x, hv.x, acc); acc = fmaf(wv.y, hv.y, acc);
            acc = fmaf(wv.z, hv.z, acc); acc = fmaf(wv.w, hv.w, acc);
        }
        h2 = fmaxf(acc, 0.f);
    }
    __syncthreads();                              // all w2 smem reads done
    // Issue wc copy; publish h2
    {
        const float4* g4 = reinterpret_cast<const float4*>(conv_w);
        #pragma unroll
        for (int v = tid; v < 7168; v += 896) {
            int row = v / 112;
            int col = v - row * 112;
            cp16(dynb + (uint32_t)(row * 113 + col) * 16u, g4 + v);
        }
        asm volatile("cp.async.commit_group;");
    }
    svb[t] = h2;
    asm volatile("cp.async.wait_group 0;");
    __syncthreads();

    // ======================= Stage 3: Wc dot + sigmoid =====================
    {
        const float4* wr = dynw + o * 113 + c * 16;
        const float4* xr = reinterpret_cast<const float4*>(svb + c * 64);
        float p = 0.f;
        #pragma unroll
        for (int k = 0; k < 16; k++) {
            float4 wv = wr[k], xv = xr[k];
            p = fmaf(wv.x, xv.x, p); p = fmaf(wv.y, xv.y, p);
            p = fmaf(wv.z, xv.z, p); p = fmaf(wv.w, xv.w, p);
        }
        red[b][t] = p;
    }
    __syncthreads();
    if (tid < 128) {
        int bb = tid >> 6, oo = tid & 63;
        float acc = s_bc[oo];
        #pragma unroll
        for (int cc = 0; cc < 7; cc++) acc += red[bb][cc * 64 + oo];
        out[bb * 64 + oo] = 1.f / (1.f + expf(-acc));
    }
}

// ---------------------------------------------------------------------------

extern "C" void kernel_launch(void* const* d_in, const int* in_sizes, int n_in,
                              void* d_out, int out_size)
{
    const float* x0 = (const float*)d_in[0];
    const float* x1 = (const float*)d_in[1];
    const float* x2 = (const float*)d_in[2];

    gap_reduce<<<5632, 256>>>(x0, x1, x2);

    const int dyn_bytes = 7616 * 16;   // 121856 B
    static int attr_set = 0;
    if (!attr_set) {
        cudaFuncSetAttribute(epilogue,
                             cudaFuncAttributeMaxDynamicSharedMemorySize,
                             dyn_bytes);
        attr_set = 1;
    }

    cudaLaunchConfig_t cfg = {};
    cfg.gridDim  = dim3(1, 1, 1);
    cfg.blockDim = dim3(896, 1, 1);
    cfg.dynamicSmemBytes = dyn_bytes;
    cudaLaunchAttribute attrs[1];
    attrs[0].id = cudaLaunchAttributeProgrammaticStreamSerialization;
    attrs[0].val.programmaticStreamSerializationAllowed = 1;
    cfg.attrs = attrs;
    cfg.numAttrs = 1;

    cudaLaunchKernelEx(&cfg, epilogue,
        (const float*)d_in[3],  (const float*)d_in[4],
        (const float*)d_in[5],  (const float*)d_in[6],
        (const float*)d_in[7],  (const float*)d_in[8],
        (const float*)d_in[9],  (const float*)d_in[10],
        (const float*)d_in[11], (const float*)d_in[12],
        (const float*)d_in[13], (const float*)d_in[14],
        (const float*)d_in[15], (const float*)d_in[16],
        (const float*)d_in[17], (const float*)d_in[18],
        (float*)d_out);
}